// round 2
// baseline (speedup 1.0000x reference)
#include <cuda_runtime.h>
#include <math.h>
#include <limits.h>

#define NMAX 200000
#define DM   128
#define VOXQ 8

// ---------------- device globals (scratch; no allocations allowed) ----------
__device__ int g_min3[3];
__device__ int g_max3[3];

struct MSParams {
    int   minc[3];
    float rcf[3];
    float rv0f, rv1f;
    int   bound;
};
__device__ MSParams g_p;

__device__ float g_value[(size_t)NMAX * DM];   // value_fea @ W_val (rows < bound)
__device__ float g_oa[(size_t)NMAX * DM];      // off|attn logits, then reused in-place for out_pre

// ---------------- tiny setup kernels ----------------------------------------
__global__ void k_init() {
    if (threadIdx.x < 3) {
        g_min3[threadIdx.x] = INT_MAX;
        g_max3[threadIdx.x] = INT_MIN;
    }
}

__global__ void k_minmax(const int* __restrict__ coords, int n) {
    int lmin0 = INT_MAX, lmin1 = INT_MAX, lmin2 = INT_MAX;
    int lmax0 = INT_MIN, lmax1 = INT_MIN, lmax2 = INT_MIN;
    for (int i = blockIdx.x * blockDim.x + threadIdx.x; i < n; i += gridDim.x * blockDim.x) {
        int c0 = coords[3*i + 0], c1 = coords[3*i + 1], c2 = coords[3*i + 2];
        lmin0 = min(lmin0, c0); lmax0 = max(lmax0, c0);
        lmin1 = min(lmin1, c1); lmax1 = max(lmax1, c1);
        lmin2 = min(lmin2, c2); lmax2 = max(lmax2, c2);
    }
    #pragma unroll
    for (int o = 16; o > 0; o >>= 1) {
        lmin0 = min(lmin0, __shfl_xor_sync(0xffffffffu, lmin0, o));
        lmin1 = min(lmin1, __shfl_xor_sync(0xffffffffu, lmin1, o));
        lmin2 = min(lmin2, __shfl_xor_sync(0xffffffffu, lmin2, o));
        lmax0 = max(lmax0, __shfl_xor_sync(0xffffffffu, lmax0, o));
        lmax1 = max(lmax1, __shfl_xor_sync(0xffffffffu, lmax1, o));
        lmax2 = max(lmax2, __shfl_xor_sync(0xffffffffu, lmax2, o));
    }
    if ((threadIdx.x & 31) == 0) {
        atomicMin(&g_min3[0], lmin0); atomicMin(&g_min3[1], lmin1); atomicMin(&g_min3[2], lmin2);
        atomicMax(&g_max3[0], lmax0); atomicMax(&g_max3[1], lmax1); atomicMax(&g_max3[2], lmax2);
    }
}

__global__ void k_params(int n) {
    if (threadIdx.x == 0 && blockIdx.x == 0) {
        int r0 = g_max3[0] - g_min3[0];
        int r1 = g_max3[1] - g_min3[1];
        int r2 = g_max3[2] - g_min3[2];
        g_p.minc[0] = g_min3[0]; g_p.minc[1] = g_min3[1]; g_p.minc[2] = g_min3[2];
        g_p.rcf[0] = (float)r0; g_p.rcf[1] = (float)r1; g_p.rcf[2] = (float)r2;
        float rv0 = (float)(r0 / VOXQ + 1);
        float rv1 = (float)(r1 / VOXQ + 1);
        g_p.rv0f = rv0; g_p.rv1f = rv1;
        // upper bound on any gather index: flat is monotone in each idx component
        float i0 = (float)r0 * 0.125f;
        float i1 = (float)r1 * 0.125f;
        float i2 = (float)r2 * 0.125f;
        float fmaxv = i0 * rv1 * rv0 + i1 * rv0 + i2;
        int b = (int)floorf(fmaxv) + 1;
        g_p.bound = (b < n) ? b : n;
    }
}

// ---------------- SGEMM: C[n x 128] = A[n x 128] @ [W1 | W2] + [b1 | b2] ----
// 128x128 block tile, 8x8 per-thread microtile, 256 threads, BK=16 staging.
__global__ __launch_bounds__(256, 2)
void k_gemm(const float* __restrict__ A,
            const float* __restrict__ W1, int w1cols,
            const float* __restrict__ W2,
            const float* __restrict__ b1, const float* __restrict__ b2,
            float* __restrict__ C, int n, int use_bound)
{
    __shared__ float As[16][132];   // transposed A tile: As[k][m]
    __shared__ float Ws[16][128];   // W tile: Ws[k][c]

    int m0 = blockIdx.x * 128;
    if (use_bound && m0 >= g_p.bound) return;

    int tid = threadIdx.x;
    int tx = tid & 15;      // column octet: cols tx*8 .. tx*8+7
    int ty = tid >> 4;      // row octet:    rows ty*8 .. ty*8+7
    int w2cols = DM - w1cols;

    float acc[8][8];
    #pragma unroll
    for (int i = 0; i < 8; i++)
        #pragma unroll
        for (int j = 0; j < 8; j++) acc[i][j] = 0.f;

    int la_r = tid >> 1;          // 0..127 : row within tile
    int la_c = (tid & 1) * 8;     // 0 or 8 : k-offset within BK

    for (int kb = 0; kb < DM; kb += 16) {
        // ---- stage A (transposed) ----
        {
            int gr = m0 + la_r;
            float4 v0 = make_float4(0.f,0.f,0.f,0.f), v1 = v0;
            if (gr < n) {
                const float* ap = A + (size_t)gr * DM + kb + la_c;
                v0 = *(const float4*)(ap);
                v1 = *(const float4*)(ap + 4);
            }
            As[la_c+0][la_r] = v0.x; As[la_c+1][la_r] = v0.y;
            As[la_c+2][la_r] = v0.z; As[la_c+3][la_r] = v0.w;
            As[la_c+4][la_r] = v1.x; As[la_c+5][la_r] = v1.y;
            As[la_c+6][la_r] = v1.z; As[la_c+7][la_r] = v1.w;
        }
        // ---- stage W (cols <w1cols from W1, rest from W2) ----
        #pragma unroll
        for (int q = 0; q < 2; q++) {
            int i = q * 256 + tid;          // 0..511 float4 slots
            int r = i >> 5;                 // 0..15
            int c = (i & 31) << 2;          // 0..124
            int gk = kb + r;
            float4 wv;
            if (c < w1cols) wv = *(const float4*)(W1 + (size_t)gk * w1cols + c);
            else            wv = *(const float4*)(W2 + (size_t)gk * w2cols + (c - w1cols));
            *(float4*)&Ws[r][c] = wv;
        }
        __syncthreads();

        #pragma unroll
        for (int k = 0; k < 16; k++) {
            float a[8], w[8];
            *(float4*)&a[0] = *(const float4*)&As[k][ty*8];
            *(float4*)&a[4] = *(const float4*)&As[k][ty*8 + 4];
            *(float4*)&w[0] = *(const float4*)&Ws[k][tx*8];
            *(float4*)&w[4] = *(const float4*)&Ws[k][tx*8 + 4];
            #pragma unroll
            for (int i = 0; i < 8; i++)
                #pragma unroll
                for (int j = 0; j < 8; j++)
                    acc[i][j] = fmaf(a[i], w[j], acc[i][j]);
        }
        __syncthreads();
    }

    float bs[8];
    #pragma unroll
    for (int j = 0; j < 8; j++) {
        int c = tx*8 + j;
        bs[j] = (c < w1cols) ? b1[c] : b2[c - w1cols];
    }
    #pragma unroll
    for (int i = 0; i < 8; i++) {
        int row = m0 + ty*8 + i;
        if (row < n) {
            float4 o0, o1;
            o0.x = acc[i][0] + bs[0]; o0.y = acc[i][1] + bs[1];
            o0.z = acc[i][2] + bs[2]; o0.w = acc[i][3] + bs[3];
            o1.x = acc[i][4] + bs[4]; o1.y = acc[i][5] + bs[5];
            o1.z = acc[i][6] + bs[6]; o1.w = acc[i][7] + bs[7];
            float* cp = C + (size_t)row * DM + tx*8;
            *(float4*)(cp)     = o0;
            *(float4*)(cp + 4) = o1;
        }
    }
}

// ---------------- epilogue: mask + softmax + gather + scale ------------------
// oa row: cols 0..95 = off logits (h*4+p)*3+d ; cols 96..127 = attn logits h*4+p
// writes out_pre in-place (row fully buffered in smem first).
__global__ __launch_bounds__(256)
void k_epi(const float* __restrict__ oa, const int* __restrict__ coords,
           const float* __restrict__ value, float* __restrict__ mid, int n)
{
    __shared__ float srow[32][132];
    __shared__ int   sg[32];

    int r0 = blockIdx.x * 32;
    int tid = threadIdx.x;

    for (int i = tid; i < 32 * 32; i += 256) {
        int r  = i >> 5;
        int c4 = (i & 31) << 2;
        int row = r0 + r;
        float4 v = make_float4(0.f,0.f,0.f,0.f);
        if (row < n) v = *(const float4*)(oa + (size_t)row * DM + c4);
        *(float4*)&srow[r][c4] = v;
    }
    __syncthreads();

    int r = tid >> 3;
    int h = tid & 7;
    int row = r0 + r;
    bool valid = row < n;
    float w = 0.f;

    if (valid) {
        if (h == 0) {
            int c0 = coords[3*row + 0], c1 = coords[3*row + 1], c2 = coords[3*row + 2];
            float i0 = (float)(c0 - g_p.minc[0]) * 0.125f;
            float i1 = (float)(c1 - g_p.minc[1]) * 0.125f;
            float i2 = (float)(c2 - g_p.minc[2]) * 0.125f;
            float flat = i0 * g_p.rv1f * g_p.rv0f + i1 * g_p.rv0f + i2;
            int gi = (int)floorf(flat);
            gi = gi < 0 ? 0 : (gi > n - 1 ? n - 1 : gi);
            sg[r] = gi;
        }
        float l[4], e[4];
        #pragma unroll
        for (int p = 0; p < 4; p++) l[p] = srow[r][96 + h*4 + p];
        float mx = fmaxf(fmaxf(l[0], l[1]), fmaxf(l[2], l[3]));
        float s = 0.f;
        #pragma unroll
        for (int p = 0; p < 4; p++) { e[p] = expf(l[p] - mx); s += e[p]; }

        float rc0 = g_p.rcf[0], rc1 = g_p.rcf[1], rc2 = g_p.rcf[2];
        float num = 0.f;
        #pragma unroll
        for (int p = 0; p < 4; p++) {
            int base = (h*4 + p) * 3;
            float t0 = (srow[r][base + 0] * rc0) * 0.5f;
            float t1 = (srow[r][base + 1] * rc1) * 0.5f;
            float t2 = (srow[r][base + 2] * rc2) * 0.5f;
            int a0 = (int)t0, a1 = (int)t1, a2 = (int)t2;   // trunc toward 0 (matches .astype(int32))
            // mask: off//8 == 0 componentwise  <=>  a in [0,7] each
            unsigned u = (unsigned)a0 | (unsigned)a1 | (unsigned)a2;
            if (u < 8u) num += e[p];
        }
        w = num / s;
    }
    __syncthreads();

    if (valid) {
        int gi = sg[r];
        const float* vp = value + (size_t)gi * DM + h*16;
        float*       mp = mid   + (size_t)row * DM + h*16;
        #pragma unroll
        for (int j = 0; j < 4; j++) {
            float4 v = *(const float4*)(vp + j*4);
            v.x *= w; v.y *= w; v.z *= w; v.w *= w;
            *(float4*)(mp + j*4) = v;
        }
    }
}

// ---------------- launcher ---------------------------------------------------
extern "C" void kernel_launch(void* const* d_in, const int* in_sizes, int n_in,
                              void* d_out, int out_size)
{
    const float* query     = (const float*)d_in[0];
    const float* value_fea = (const float*)d_in[1];
    const int*   coords    = (const int*)  d_in[2];
    const float* W_off     = (const float*)d_in[3];
    const float* b_off     = (const float*)d_in[4];
    const float* W_attn    = (const float*)d_in[5];
    const float* b_attn    = (const float*)d_in[6];
    const float* W_val     = (const float*)d_in[7];
    const float* b_val     = (const float*)d_in[8];
    const float* W_out     = (const float*)d_in[9];
    const float* b_out     = (const float*)d_in[10];
    float* out = (float*)d_out;

    int n = in_sizes[0] / DM;
    if (n > NMAX) n = NMAX;

    float *gv = nullptr, *goa = nullptr;
    cudaGetSymbolAddress((void**)&gv,  g_value);
    cudaGetSymbolAddress((void**)&goa, g_oa);

    int nb = (n + 127) / 128;

    k_init  <<<1, 32>>>();
    k_minmax<<<592, 256>>>(coords, n);
    k_params<<<1, 1>>>(n);

    // value = value_fea @ W_val + b_val (only rows < bound are ever gathered)
    k_gemm<<<nb, 256>>>(value_fea, W_val, DM, W_val, b_val, b_val, gv, n, 1);

    // [off | attn] = query @ [W_off | W_attn] + [b_off | b_attn]
    k_gemm<<<nb, 256>>>(query, W_off, 96, W_attn, b_off, b_attn, goa, n, 0);

    // per-row mask/softmax/gather/scale -> out_pre (in-place in goa)
    k_epi<<<(n + 31) / 32, 256>>>(goa, coords, gv, goa, n);

    // out = out_pre @ W_out + b_out
    k_gemm<<<nb, 256>>>(goa, W_out, DM, W_out, b_out, b_out, out, n, 0);
}

// round 5
// speedup vs baseline: 1.3202x; 1.3202x over previous
#include <cuda_runtime.h>
#include <math.h>
#include <limits.h>

#define NMAX 200000
#define DM   128
#define VOXQ 8

// ---------------- device globals (scratch; no allocations allowed) ----------
__device__ int g_min3[3];
__device__ int g_max3[3];

struct MSParams {
    int   minc[3];
    float rcf[3];
    float rv0f, rv1f;
    int   bound;
};
__device__ MSParams g_p;

__device__ float g_value[(size_t)NMAX * DM];  // value_fea @ W_val (rows < bound used)
__device__ float g_oa[(size_t)NMAX * DM];     // [off | attn] logits
__device__ float g_w8[(size_t)NMAX * 8];      // per-row per-head weight
__device__ int   g_gi[(size_t)NMAX];          // per-row gather index

// ---------------- tiny setup kernels ----------------------------------------
__global__ void k_init() {
    if (threadIdx.x < 3) {
        g_min3[threadIdx.x] = INT_MAX;
        g_max3[threadIdx.x] = INT_MIN;
    }
}

__global__ void k_minmax(const int* __restrict__ coords, int n) {
    int lmin0 = INT_MAX, lmin1 = INT_MAX, lmin2 = INT_MAX;
    int lmax0 = INT_MIN, lmax1 = INT_MIN, lmax2 = INT_MIN;
    for (int i = blockIdx.x * blockDim.x + threadIdx.x; i < n; i += gridDim.x * blockDim.x) {
        int c0 = coords[3*i + 0], c1 = coords[3*i + 1], c2 = coords[3*i + 2];
        lmin0 = min(lmin0, c0); lmax0 = max(lmax0, c0);
        lmin1 = min(lmin1, c1); lmax1 = max(lmax1, c1);
        lmin2 = min(lmin2, c2); lmax2 = max(lmax2, c2);
    }
    #pragma unroll
    for (int o = 16; o > 0; o >>= 1) {
        lmin0 = min(lmin0, __shfl_xor_sync(0xffffffffu, lmin0, o));
        lmin1 = min(lmin1, __shfl_xor_sync(0xffffffffu, lmin1, o));
        lmin2 = min(lmin2, __shfl_xor_sync(0xffffffffu, lmin2, o));
        lmax0 = max(lmax0, __shfl_xor_sync(0xffffffffu, lmax0, o));
        lmax1 = max(lmax1, __shfl_xor_sync(0xffffffffu, lmax1, o));
        lmax2 = max(lmax2, __shfl_xor_sync(0xffffffffu, lmax2, o));
    }
    if ((threadIdx.x & 31) == 0) {
        atomicMin(&g_min3[0], lmin0); atomicMin(&g_min3[1], lmin1); atomicMin(&g_min3[2], lmin2);
        atomicMax(&g_max3[0], lmax0); atomicMax(&g_max3[1], lmax1); atomicMax(&g_max3[2], lmax2);
    }
}

__global__ void k_params(int n) {
    if (threadIdx.x == 0 && blockIdx.x == 0) {
        int r0 = g_max3[0] - g_min3[0];
        int r1 = g_max3[1] - g_min3[1];
        int r2 = g_max3[2] - g_min3[2];
        g_p.minc[0] = g_min3[0]; g_p.minc[1] = g_min3[1]; g_p.minc[2] = g_min3[2];
        g_p.rcf[0] = (float)r0; g_p.rcf[1] = (float)r1; g_p.rcf[2] = (float)r2;
        float rv0 = (float)(r0 / VOXQ + 1);
        float rv1 = (float)(r1 / VOXQ + 1);
        g_p.rv0f = rv0; g_p.rv1f = rv1;
        float i0 = (float)r0 * 0.125f;
        float i1 = (float)r1 * 0.125f;
        float i2 = (float)r2 * 0.125f;
        float fmaxv = i0 * rv1 * rv0 + i1 * rv0 + i2;
        int b = (int)floorf(fmaxv) + 1;
        g_p.bound = (b < n) ? b : n;
    }
}

// ---------------- SGEMM: C = A @ [W1|W2] + [b1|b2] ---------------------------
// 128x128 tile, 8x8 microtile, 256 threads, BK=16, register prefetch.
// Thread cols: [tx*4..+3] and [64+tx*4..+3] -> conflict-free LDS.128.
__global__ __launch_bounds__(256, 2)
void k_gemm(const float* __restrict__ A,
            const float* __restrict__ W1, int w1cols,
            const float* __restrict__ W2,
            const float* __restrict__ b1, const float* __restrict__ b2,
            float* __restrict__ C, int n, int use_bound)
{
    __shared__ float As[16 * 132];   // As[k][m]
    __shared__ float Ws[16 * 128];   // Ws[k][c]

    int m0 = blockIdx.x * 128;
    if (use_bound && m0 >= g_p.bound) return;

    int tid = threadIdx.x;
    int tx = tid & 15, ty = tid >> 4;
    int w2cols = DM - w1cols;

    float acc[8][8];
    #pragma unroll
    for (int i = 0; i < 8; i++)
        #pragma unroll
        for (int j = 0; j < 8; j++) acc[i][j] = 0.f;

    int la_r = tid >> 1;
    int la_c = (tid & 1) * 8;
    int gr = m0 + la_r;
    const float* aRow = (gr < n) ? (A + (size_t)gr * DM + la_c) : (const float*)0;
    int rW = tid >> 5;              // 0..7
    int cW = (tid & 31) << 2;       // 0..124

    float4 pa0 = make_float4(0,0,0,0), pa1 = pa0, pw0, pw1;
    if (aRow) { pa0 = *(const float4*)(aRow); pa1 = *(const float4*)(aRow + 4); }
    pw0 = (cW < w1cols) ? *(const float4*)(W1 + (size_t)rW * w1cols + cW)
                        : *(const float4*)(W2 + (size_t)rW * w2cols + (cW - w1cols));
    pw1 = (cW < w1cols) ? *(const float4*)(W1 + (size_t)(rW+8) * w1cols + cW)
                        : *(const float4*)(W2 + (size_t)(rW+8) * w2cols + (cW - w1cols));

    #pragma unroll 1
    for (int kb = 0; kb < 8; kb++) {
        As[(la_c+0)*132 + la_r] = pa0.x; As[(la_c+1)*132 + la_r] = pa0.y;
        As[(la_c+2)*132 + la_r] = pa0.z; As[(la_c+3)*132 + la_r] = pa0.w;
        As[(la_c+4)*132 + la_r] = pa1.x; As[(la_c+5)*132 + la_r] = pa1.y;
        As[(la_c+6)*132 + la_r] = pa1.z; As[(la_c+7)*132 + la_r] = pa1.w;
        *(float4*)&Ws[rW * 128 + cW]       = pw0;
        *(float4*)&Ws[(rW + 8) * 128 + cW] = pw1;
        __syncthreads();

        if (kb < 7) {
            int ko = (kb + 1) * 16;
            if (aRow) { pa0 = *(const float4*)(aRow + ko); pa1 = *(const float4*)(aRow + ko + 4); }
            pw0 = (cW < w1cols) ? *(const float4*)(W1 + (size_t)(ko+rW) * w1cols + cW)
                                : *(const float4*)(W2 + (size_t)(ko+rW) * w2cols + (cW - w1cols));
            pw1 = (cW < w1cols) ? *(const float4*)(W1 + (size_t)(ko+rW+8) * w1cols + cW)
                                : *(const float4*)(W2 + (size_t)(ko+rW+8) * w2cols + (cW - w1cols));
        }

        #pragma unroll
        for (int k = 0; k < 16; k++) {
            float a[8], w[8];
            *(float4*)&a[0] = *(const float4*)&As[k*132 + ty*8];
            *(float4*)&a[4] = *(const float4*)&As[k*132 + ty*8 + 4];
            *(float4*)&w[0] = *(const float4*)&Ws[k*128 + tx*4];
            *(float4*)&w[4] = *(const float4*)&Ws[k*128 + 64 + tx*4];
            #pragma unroll
            for (int i = 0; i < 8; i++)
                #pragma unroll
                for (int j = 0; j < 8; j++)
                    acc[i][j] = fmaf(a[i], w[j], acc[i][j]);
        }
        __syncthreads();
    }

    float bs0[4], bs1[4];
    #pragma unroll
    for (int j = 0; j < 4; j++) {
        int c0 = tx*4 + j, c1 = 64 + tx*4 + j;
        bs0[j] = (c0 < w1cols) ? b1[c0] : b2[c0 - w1cols];
        bs1[j] = (c1 < w1cols) ? b1[c1] : b2[c1 - w1cols];
    }
    #pragma unroll
    for (int i = 0; i < 8; i++) {
        int row = m0 + ty*8 + i;
        if (row < n) {
            float4 o0, o1;
            o0.x = acc[i][0] + bs0[0]; o0.y = acc[i][1] + bs0[1];
            o0.z = acc[i][2] + bs0[2]; o0.w = acc[i][3] + bs0[3];
            o1.x = acc[i][4] + bs1[0]; o1.y = acc[i][5] + bs1[1];
            o1.z = acc[i][6] + bs1[2]; o1.w = acc[i][7] + bs1[3];
            float* cp = C + (size_t)row * DM;
            *(float4*)(cp + tx*4)      = o0;
            *(float4*)(cp + 64 + tx*4) = o1;
        }
    }
}

// ---------------- epilogue: mask + softmax -> w8[n][8], gi[n] ----------------
__global__ __launch_bounds__(256)
void k_epi(const float* __restrict__ oa, const int* __restrict__ coords,
           float* __restrict__ w8, int* __restrict__ gi_out, int n)
{
    __shared__ float srow[32][132];

    int r0 = blockIdx.x * 32;
    int tid = threadIdx.x;

    for (int i = tid; i < 32 * 32; i += 256) {
        int r  = i >> 5;
        int c4 = (i & 31) << 2;
        int row = r0 + r;
        float4 v = make_float4(0.f,0.f,0.f,0.f);
        if (row < n) v = *(const float4*)(oa + (size_t)row * DM + c4);
        *(float4*)&srow[r][c4] = v;
    }
    __syncthreads();

    int r = tid >> 3;
    int h = tid & 7;
    int row = r0 + r;
    if (row >= n) return;

    if (h == 0) {
        int c0 = coords[3*row + 0], c1 = coords[3*row + 1], c2 = coords[3*row + 2];
        float i0 = (float)(c0 - g_p.minc[0]) * 0.125f;
        float i1 = (float)(c1 - g_p.minc[1]) * 0.125f;
        float i2 = (float)(c2 - g_p.minc[2]) * 0.125f;
        float flat = i0 * g_p.rv1f * g_p.rv0f + i1 * g_p.rv0f + i2;
        int gi = (int)floorf(flat);
        gi = gi < 0 ? 0 : (gi > n - 1 ? n - 1 : gi);
        gi_out[row] = gi;
    }

    float l[4], e[4];
    #pragma unroll
    for (int p = 0; p < 4; p++) l[p] = srow[r][96 + h*4 + p];
    float mx = fmaxf(fmaxf(l[0], l[1]), fmaxf(l[2], l[3]));
    float s = 0.f;
    #pragma unroll
    for (int p = 0; p < 4; p++) { e[p] = expf(l[p] - mx); s += e[p]; }

    float rc0 = g_p.rcf[0], rc1 = g_p.rcf[1], rc2 = g_p.rcf[2];
    float num = 0.f;
    #pragma unroll
    for (int p = 0; p < 4; p++) {
        int base = (h*4 + p) * 3;
        float t0 = (srow[r][base + 0] * rc0) * 0.5f;
        float t1 = (srow[r][base + 1] * rc1) * 0.5f;
        float t2 = (srow[r][base + 2] * rc2) * 0.5f;
        int a0 = (int)t0, a1 = (int)t1, a2 = (int)t2;   // trunc toward 0 (.astype(int32))
        unsigned u = (unsigned)a0 | (unsigned)a1 | (unsigned)a2;
        if (u < 8u) num += e[p];
    }
    w8[(size_t)row * 8 + h] = num / s;
}

// ---------------- out-GEMM with gathered A: out = (w ⊙ value[gi]) @ W_out + b
__global__ __launch_bounds__(256, 2)
void k_out(const float* __restrict__ w8, const int* __restrict__ gidx,
           const float* __restrict__ value, const float* __restrict__ W_out,
           const float* __restrict__ b_out, float* __restrict__ out, int n)
{
    __shared__ float As[16 * 132];
    __shared__ float Ws[16 * 128];

    int m0 = blockIdx.x * 128;
    int tid = threadIdx.x;
    int tx = tid & 15, ty = tid >> 4;

    float acc[8][8];
    #pragma unroll
    for (int i = 0; i < 8; i++)
        #pragma unroll
        for (int j = 0; j < 8; j++) acc[i][j] = 0.f;

    int la_r = tid >> 1;
    int la_c = (tid & 1) * 8;
    int row = m0 + la_r;
    bool v = row < n;

    float wloc[8];
    #pragma unroll
    for (int h = 0; h < 8; h++) wloc[h] = 0.f;
    const float* vrow = value;     // safe default
    if (v) {
        int gi = gidx[row];
        vrow = value + (size_t)gi * DM;
        #pragma unroll
        for (int h = 0; h < 8; h++) wloc[h] = w8[(size_t)row * 8 + h];
    }

    int rW = tid >> 5;
    int cW = (tid & 31) << 2;

    float4 pa0 = make_float4(0,0,0,0), pa1 = pa0, pw0, pw1;
    if (v) { pa0 = *(const float4*)(vrow + la_c); pa1 = *(const float4*)(vrow + la_c + 4); }
    pw0 = *(const float4*)(W_out + (size_t)rW * DM + cW);
    pw1 = *(const float4*)(W_out + (size_t)(rW + 8) * DM + cW);

    #pragma unroll 1
    for (int kb = 0; kb < 8; kb++) {
        // head index for k = kb*16 + la_c + j (j<8, la_c in {0,8}) is exactly kb
        float sc = wloc[kb];
        As[(la_c+0)*132 + la_r] = pa0.x * sc; As[(la_c+1)*132 + la_r] = pa0.y * sc;
        As[(la_c+2)*132 + la_r] = pa0.z * sc; As[(la_c+3)*132 + la_r] = pa0.w * sc;
        As[(la_c+4)*132 + la_r] = pa1.x * sc; As[(la_c+5)*132 + la_r] = pa1.y * sc;
        As[(la_c+6)*132 + la_r] = pa1.z * sc; As[(la_c+7)*132 + la_r] = pa1.w * sc;
        *(float4*)&Ws[rW * 128 + cW]       = pw0;
        *(float4*)&Ws[(rW + 8) * 128 + cW] = pw1;
        __syncthreads();

        if (kb < 7) {
            int ko = (kb + 1) * 16;
            if (v) { pa0 = *(const float4*)(vrow + ko + la_c); pa1 = *(const float4*)(vrow + ko + la_c + 4); }
            pw0 = *(const float4*)(W_out + (size_t)(ko + rW) * DM + cW);
            pw1 = *(const float4*)(W_out + (size_t)(ko + rW + 8) * DM + cW);
        }

        #pragma unroll
        for (int k = 0; k < 16; k++) {
            float a[8], w[8];
            *(float4*)&a[0] = *(const float4*)&As[k*132 + ty*8];
            *(float4*)&a[4] = *(const float4*)&As[k*132 + ty*8 + 4];
            *(float4*)&w[0] = *(const float4*)&Ws[k*128 + tx*4];
            *(float4*)&w[4] = *(const float4*)&Ws[k*128 + 64 + tx*4];
            #pragma unroll
            for (int i = 0; i < 8; i++)
                #pragma unroll
                for (int j = 0; j < 8; j++)
                    acc[i][j] = fmaf(a[i], w[j], acc[i][j]);
        }
        __syncthreads();
    }

    float4 b0 = *(const float4*)(b_out + tx*4);
    float4 b1 = *(const float4*)(b_out + 64 + tx*4);
    #pragma unroll
    for (int i = 0; i < 8; i++) {
        int orow = m0 + ty*8 + i;
        if (orow < n) {
            float4 o0, o1;
            o0.x = acc[i][0] + b0.x; o0.y = acc[i][1] + b0.y;
            o0.z = acc[i][2] + b0.z; o0.w = acc[i][3] + b0.w;
            o1.x = acc[i][4] + b1.x; o1.y = acc[i][5] + b1.y;
            o1.z = acc[i][6] + b1.z; o1.w = acc[i][7] + b1.w;
            float* cp = out + (size_t)orow * DM;
            *(float4*)(cp + tx*4)      = o0;
            *(float4*)(cp + 64 + tx*4) = o1;
        }
    }
}

// ---------------- launcher ---------------------------------------------------
extern "C" void kernel_launch(void* const* d_in, const int* in_sizes, int n_in,
                              void* d_out, int out_size)
{
    const float* query     = (const float*)d_in[0];
    const float* value_fea = (const float*)d_in[1];
    const int*   coords    = (const int*)  d_in[2];
    const float* W_off     = (const float*)d_in[3];
    const float* b_off     = (const float*)d_in[4];
    const float* W_attn    = (const float*)d_in[5];
    const float* b_attn    = (const float*)d_in[6];
    const float* W_val     = (const float*)d_in[7];
    const float* b_val     = (const float*)d_in[8];
    const float* W_out     = (const float*)d_in[9];
    const float* b_out     = (const float*)d_in[10];
    float* out = (float*)d_out;

    int n = in_sizes[0] / DM;
    if (n > NMAX) n = NMAX;

    float *gv = nullptr, *goa = nullptr, *gw = nullptr;
    int *ggi = nullptr;
    cudaGetSymbolAddress((void**)&gv,  g_value);
    cudaGetSymbolAddress((void**)&goa, g_oa);
    cudaGetSymbolAddress((void**)&gw,  g_w8);
    cudaGetSymbolAddress((void**)&ggi, g_gi);

    int nb = (n + 127) / 128;

    k_init  <<<1, 32>>>();
    k_minmax<<<592, 256>>>(coords, n);
    k_params<<<1, 1>>>(n);

    // value = value_fea @ W_val + b_val (only rows < bound are gathered)
    k_gemm<<<nb, 256>>>(value_fea, W_val, DM, W_val, b_val, b_val, gv, n, 1);

    // [off | attn] = query @ [W_off | W_attn] + [b_off | b_attn]
    k_gemm<<<nb, 256>>>(query, W_off, 96, W_attn, b_off, b_attn, goa, n, 0);

    // per-row mask/softmax -> w8, gather index -> gi
    k_epi<<<(n + 31) / 32, 256>>>(goa, coords, gw, ggi, n);

    // out = (w ⊙ value[gi]) @ W_out + b_out  (gathered A, no out_pre round trip)
    k_out<<<nb, 256>>>(gw, ggi, gv, W_out, b_out, out, n);
}

// round 6
// speedup vs baseline: 1.4383x; 1.0894x over previous
#include <cuda_runtime.h>
#include <math.h>
#include <limits.h>

#define NMAX 200000
#define DM   128
#define VOXQ 8

// packed dual-fp32 FMA (sm_100+): each 32-bit lane is a full rn FMA
#define FMA2(acc, a, w) \
    asm("fma.rn.f32x2 %0, %1, %2, %0;" : "+l"(acc) : "l"(a), "l"(w))
#define BCAST2(dst, fv) \
    asm("mov.b64 %0, {%1, %1};" : "=l"(dst) : "r"(__float_as_uint(fv)))

__device__ __forceinline__ float f2lo(unsigned long long v) {
    return __uint_as_float((unsigned)v);
}
__device__ __forceinline__ float f2hi(unsigned long long v) {
    return __uint_as_float((unsigned)(v >> 32));
}

// ---------------- device globals (scratch; no allocations allowed) ----------
__device__ int g_min3[3];
__device__ int g_max3[3];

struct MSParams {
    int   minc[3];
    float rcf[3];
    float rv0f, rv1f;
    int   bound;
};
__device__ MSParams g_p;

__device__ float g_value[(size_t)NMAX * DM];  // value_fea @ W_val (rows < bound used)
__device__ float g_oa[(size_t)NMAX * DM];     // [off | attn] logits
__device__ float g_w8[(size_t)NMAX * 8];      // per-row per-head weight
__device__ int   g_gi[(size_t)NMAX];          // per-row gather index

// ---------------- tiny setup kernels ----------------------------------------
__global__ void k_init() {
    if (threadIdx.x < 3) {
        g_min3[threadIdx.x] = INT_MAX;
        g_max3[threadIdx.x] = INT_MIN;
    }
}

__global__ void k_minmax(const int* __restrict__ coords, int n) {
    int lmin0 = INT_MAX, lmin1 = INT_MAX, lmin2 = INT_MAX;
    int lmax0 = INT_MIN, lmax1 = INT_MIN, lmax2 = INT_MIN;
    for (int i = blockIdx.x * blockDim.x + threadIdx.x; i < n; i += gridDim.x * blockDim.x) {
        int c0 = coords[3*i + 0], c1 = coords[3*i + 1], c2 = coords[3*i + 2];
        lmin0 = min(lmin0, c0); lmax0 = max(lmax0, c0);
        lmin1 = min(lmin1, c1); lmax1 = max(lmax1, c1);
        lmin2 = min(lmin2, c2); lmax2 = max(lmax2, c2);
    }
    #pragma unroll
    for (int o = 16; o > 0; o >>= 1) {
        lmin0 = min(lmin0, __shfl_xor_sync(0xffffffffu, lmin0, o));
        lmin1 = min(lmin1, __shfl_xor_sync(0xffffffffu, lmin1, o));
        lmin2 = min(lmin2, __shfl_xor_sync(0xffffffffu, lmin2, o));
        lmax0 = max(lmax0, __shfl_xor_sync(0xffffffffu, lmax0, o));
        lmax1 = max(lmax1, __shfl_xor_sync(0xffffffffu, lmax1, o));
        lmax2 = max(lmax2, __shfl_xor_sync(0xffffffffu, lmax2, o));
    }
    if ((threadIdx.x & 31) == 0) {
        atomicMin(&g_min3[0], lmin0); atomicMin(&g_min3[1], lmin1); atomicMin(&g_min3[2], lmin2);
        atomicMax(&g_max3[0], lmax0); atomicMax(&g_max3[1], lmax1); atomicMax(&g_max3[2], lmax2);
    }
}

__global__ void k_params(int n) {
    if (threadIdx.x == 0 && blockIdx.x == 0) {
        int r0 = g_max3[0] - g_min3[0];
        int r1 = g_max3[1] - g_min3[1];
        int r2 = g_max3[2] - g_min3[2];
        g_p.minc[0] = g_min3[0]; g_p.minc[1] = g_min3[1]; g_p.minc[2] = g_min3[2];
        g_p.rcf[0] = (float)r0; g_p.rcf[1] = (float)r1; g_p.rcf[2] = (float)r2;
        float rv0 = (float)(r0 / VOXQ + 1);
        float rv1 = (float)(r1 / VOXQ + 1);
        g_p.rv0f = rv0; g_p.rv1f = rv1;
        float i0 = (float)r0 * 0.125f;
        float i1 = (float)r1 * 0.125f;
        float i2 = (float)r2 * 0.125f;
        float fmaxv = i0 * rv1 * rv0 + i1 * rv0 + i2;
        int b = (int)floorf(fmaxv) + 1;
        g_p.bound = (b < n) ? b : n;
    }
}

// ---------------- SGEMM: C = A @ [W1|W2] + [b1|b2] ---------------------------
// 128x128 tile, 8x8 microtile as 8x(4 f32x2), 256 threads, BK=16, prefetch.
// Thread cols: [tx*4..+3] and [64+tx*4..+3] -> conflict-free LDS, W pairs free.
__global__ __launch_bounds__(256, 2)
void k_gemm(const float* __restrict__ A,
            const float* __restrict__ W1, int w1cols,
            const float* __restrict__ W2,
            const float* __restrict__ b1, const float* __restrict__ b2,
            float* __restrict__ C, int n, int use_bound)
{
    __shared__ __align__(16) float As[16 * 132];   // As[k][m]
    __shared__ __align__(16) float Ws[16 * 128];   // Ws[k][c]

    int m0 = blockIdx.x * 128;
    if (use_bound && m0 >= g_p.bound) return;

    int tid = threadIdx.x;
    int tx = tid & 15, ty = tid >> 4;
    int w2cols = DM - w1cols;

    unsigned long long acc[8][4];
    #pragma unroll
    for (int i = 0; i < 8; i++)
        #pragma unroll
        for (int j = 0; j < 4; j++) acc[i][j] = 0ull;

    int la_r = tid >> 1;
    int la_c = (tid & 1) * 8;
    int gr = m0 + la_r;
    const float* aRow = (gr < n) ? (A + (size_t)gr * DM + la_c) : (const float*)0;
    int rW = tid >> 5;              // 0..7
    int cW = (tid & 31) << 2;       // 0..124

    float4 pa0 = make_float4(0,0,0,0), pa1 = pa0, pw0, pw1;
    if (aRow) { pa0 = *(const float4*)(aRow); pa1 = *(const float4*)(aRow + 4); }
    pw0 = (cW < w1cols) ? *(const float4*)(W1 + (size_t)rW * w1cols + cW)
                        : *(const float4*)(W2 + (size_t)rW * w2cols + (cW - w1cols));
    pw1 = (cW < w1cols) ? *(const float4*)(W1 + (size_t)(rW+8) * w1cols + cW)
                        : *(const float4*)(W2 + (size_t)(rW+8) * w2cols + (cW - w1cols));

    #pragma unroll 1
    for (int kb = 0; kb < 8; kb++) {
        As[(la_c+0)*132 + la_r] = pa0.x; As[(la_c+1)*132 + la_r] = pa0.y;
        As[(la_c+2)*132 + la_r] = pa0.z; As[(la_c+3)*132 + la_r] = pa0.w;
        As[(la_c+4)*132 + la_r] = pa1.x; As[(la_c+5)*132 + la_r] = pa1.y;
        As[(la_c+6)*132 + la_r] = pa1.z; As[(la_c+7)*132 + la_r] = pa1.w;
        *(float4*)&Ws[rW * 128 + cW]       = pw0;
        *(float4*)&Ws[(rW + 8) * 128 + cW] = pw1;
        __syncthreads();

        if (kb < 7) {
            int ko = (kb + 1) * 16;
            if (aRow) { pa0 = *(const float4*)(aRow + ko); pa1 = *(const float4*)(aRow + ko + 4); }
            pw0 = (cW < w1cols) ? *(const float4*)(W1 + (size_t)(ko+rW) * w1cols + cW)
                                : *(const float4*)(W2 + (size_t)(ko+rW) * w2cols + (cW - w1cols));
            pw1 = (cW < w1cols) ? *(const float4*)(W1 + (size_t)(ko+rW+8) * w1cols + cW)
                                : *(const float4*)(W2 + (size_t)(ko+rW+8) * w2cols + (cW - w1cols));
        }

        #pragma unroll
        for (int k = 0; k < 16; k++) {
            float4 aA = *(const float4*)&As[k*132 + ty*8];
            float4 aB = *(const float4*)&As[k*132 + ty*8 + 4];
            ulonglong2 wA = *(const ulonglong2*)&Ws[k*128 + tx*4];
            ulonglong2 wB = *(const ulonglong2*)&Ws[k*128 + 64 + tx*4];
            unsigned long long wp0 = wA.x, wp1 = wA.y, wp2 = wB.x, wp3 = wB.y;
            float av[8] = {aA.x, aA.y, aA.z, aA.w, aB.x, aB.y, aB.z, aB.w};
            #pragma unroll
            for (int i = 0; i < 8; i++) {
                unsigned long long a2;
                BCAST2(a2, av[i]);
                FMA2(acc[i][0], a2, wp0);
                FMA2(acc[i][1], a2, wp1);
                FMA2(acc[i][2], a2, wp2);
                FMA2(acc[i][3], a2, wp3);
            }
        }
        __syncthreads();
    }

    float bs0[4], bs1[4];
    #pragma unroll
    for (int j = 0; j < 4; j++) {
        int c0 = tx*4 + j, c1 = 64 + tx*4 + j;
        bs0[j] = (c0 < w1cols) ? b1[c0] : b2[c0 - w1cols];
        bs1[j] = (c1 < w1cols) ? b1[c1] : b2[c1 - w1cols];
    }
    #pragma unroll
    for (int i = 0; i < 8; i++) {
        int row = m0 + ty*8 + i;
        if (row < n) {
            float4 o0, o1;
            o0.x = f2lo(acc[i][0]) + bs0[0]; o0.y = f2hi(acc[i][0]) + bs0[1];
            o0.z = f2lo(acc[i][1]) + bs0[2]; o0.w = f2hi(acc[i][1]) + bs0[3];
            o1.x = f2lo(acc[i][2]) + bs1[0]; o1.y = f2hi(acc[i][2]) + bs1[1];
            o1.z = f2lo(acc[i][3]) + bs1[2]; o1.w = f2hi(acc[i][3]) + bs1[3];
            float* cp = C + (size_t)row * DM;
            *(float4*)(cp + tx*4)      = o0;
            *(float4*)(cp + 64 + tx*4) = o1;
        }
    }
}

// ---------------- epilogue: mask + softmax -> w8[n][8], gi[n] ----------------
__global__ __launch_bounds__(256)
void k_epi(const float* __restrict__ oa, const int* __restrict__ coords,
           float* __restrict__ w8, int* __restrict__ gi_out, int n)
{
    __shared__ __align__(16) float srow[32][132];

    int r0 = blockIdx.x * 32;
    int tid = threadIdx.x;

    for (int i = tid; i < 32 * 32; i += 256) {
        int r  = i >> 5;
        int c4 = (i & 31) << 2;
        int row = r0 + r;
        float4 v = make_float4(0.f,0.f,0.f,0.f);
        if (row < n) v = *(const float4*)(oa + (size_t)row * DM + c4);
        *(float4*)&srow[r][c4] = v;
    }
    __syncthreads();

    int r = tid >> 3;
    int h = tid & 7;
    int row = r0 + r;
    if (row >= n) return;

    if (h == 0) {
        int c0 = coords[3*row + 0], c1 = coords[3*row + 1], c2 = coords[3*row + 2];
        float i0 = (float)(c0 - g_p.minc[0]) * 0.125f;
        float i1 = (float)(c1 - g_p.minc[1]) * 0.125f;
        float i2 = (float)(c2 - g_p.minc[2]) * 0.125f;
        float flat = i0 * g_p.rv1f * g_p.rv0f + i1 * g_p.rv0f + i2;
        int gi = (int)floorf(flat);
        gi = gi < 0 ? 0 : (gi > n - 1 ? n - 1 : gi);
        gi_out[row] = gi;
    }

    float l[4], e[4];
    #pragma unroll
    for (int p = 0; p < 4; p++) l[p] = srow[r][96 + h*4 + p];
    float mx = fmaxf(fmaxf(l[0], l[1]), fmaxf(l[2], l[3]));
    float s = 0.f;
    #pragma unroll
    for (int p = 0; p < 4; p++) { e[p] = expf(l[p] - mx); s += e[p]; }

    float rc0 = g_p.rcf[0], rc1 = g_p.rcf[1], rc2 = g_p.rcf[2];
    float num = 0.f;
    #pragma unroll
    for (int p = 0; p < 4; p++) {
        int base = (h*4 + p) * 3;
        float t0 = (srow[r][base + 0] * rc0) * 0.5f;
        float t1 = (srow[r][base + 1] * rc1) * 0.5f;
        float t2 = (srow[r][base + 2] * rc2) * 0.5f;
        int a0 = (int)t0, a1 = (int)t1, a2 = (int)t2;   // trunc toward 0 (.astype(int32))
        unsigned u = (unsigned)a0 | (unsigned)a1 | (unsigned)a2;
        if (u < 8u) num += e[p];
    }
    w8[(size_t)row * 8 + h] = num / s;
}

// ---------------- out-GEMM with gathered A: out = (w ⊙ value[gi]) @ W_out + b
__global__ __launch_bounds__(256, 2)
void k_out(const float* __restrict__ w8, const int* __restrict__ gidx,
           const float* __restrict__ value, const float* __restrict__ W_out,
           const float* __restrict__ b_out, float* __restrict__ out, int n)
{
    __shared__ __align__(16) float As[16 * 132];
    __shared__ __align__(16) float Ws[16 * 128];

    int m0 = blockIdx.x * 128;
    int tid = threadIdx.x;
    int tx = tid & 15, ty = tid >> 4;

    unsigned long long acc[8][4];
    #pragma unroll
    for (int i = 0; i < 8; i++)
        #pragma unroll
        for (int j = 0; j < 4; j++) acc[i][j] = 0ull;

    int la_r = tid >> 1;
    int la_c = (tid & 1) * 8;
    int row = m0 + la_r;
    bool v = row < n;

    float wloc[8];
    #pragma unroll
    for (int h = 0; h < 8; h++) wloc[h] = 0.f;
    const float* vrow = value;     // safe default
    if (v) {
        int gi = gidx[row];
        vrow = value + (size_t)gi * DM;
        #pragma unroll
        for (int h = 0; h < 8; h++) wloc[h] = w8[(size_t)row * 8 + h];
    }

    int rW = tid >> 5;
    int cW = (tid & 31) << 2;

    float4 pa0 = make_float4(0,0,0,0), pa1 = pa0, pw0, pw1;
    if (v) { pa0 = *(const float4*)(vrow + la_c); pa1 = *(const float4*)(vrow + la_c + 4); }
    pw0 = *(const float4*)(W_out + (size_t)rW * DM + cW);
    pw1 = *(const float4*)(W_out + (size_t)(rW + 8) * DM + cW);

    #pragma unroll 1
    for (int kb = 0; kb < 8; kb++) {
        // head index for k = kb*16 + la_c + j (j<8, la_c in {0,8}) is exactly kb
        float sc = wloc[kb];
        As[(la_c+0)*132 + la_r] = pa0.x * sc; As[(la_c+1)*132 + la_r] = pa0.y * sc;
        As[(la_c+2)*132 + la_r] = pa0.z * sc; As[(la_c+3)*132 + la_r] = pa0.w * sc;
        As[(la_c+4)*132 + la_r] = pa1.x * sc; As[(la_c+5)*132 + la_r] = pa1.y * sc;
        As[(la_c+6)*132 + la_r] = pa1.z * sc; As[(la_c+7)*132 + la_r] = pa1.w * sc;
        *(float4*)&Ws[rW * 128 + cW]       = pw0;
        *(float4*)&Ws[(rW + 8) * 128 + cW] = pw1;
        __syncthreads();

        if (kb < 7) {
            int ko = (kb + 1) * 16;
            if (v) { pa0 = *(const float4*)(vrow + ko + la_c); pa1 = *(const float4*)(vrow + ko + la_c + 4); }
            pw0 = *(const float4*)(W_out + (size_t)(ko + rW) * DM + cW);
            pw1 = *(const float4*)(W_out + (size_t)(ko + rW + 8) * DM + cW);
        }

        #pragma unroll
        for (int k = 0; k < 16; k++) {
            float4 aA = *(const float4*)&As[k*132 + ty*8];
            float4 aB = *(const float4*)&As[k*132 + ty*8 + 4];
            ulonglong2 wA = *(const ulonglong2*)&Ws[k*128 + tx*4];
            ulonglong2 wB = *(const ulonglong2*)&Ws[k*128 + 64 + tx*4];
            unsigned long long wp0 = wA.x, wp1 = wA.y, wp2 = wB.x, wp3 = wB.y;
            float av[8] = {aA.x, aA.y, aA.z, aA.w, aB.x, aB.y, aB.z, aB.w};
            #pragma unroll
            for (int i = 0; i < 8; i++) {
                unsigned long long a2;
                BCAST2(a2, av[i]);
                FMA2(acc[i][0], a2, wp0);
                FMA2(acc[i][1], a2, wp1);
                FMA2(acc[i][2], a2, wp2);
                FMA2(acc[i][3], a2, wp3);
            }
        }
        __syncthreads();
    }

    float4 b0 = *(const float4*)(b_out + tx*4);
    float4 b1 = *(const float4*)(b_out + 64 + tx*4);
    #pragma unroll
    for (int i = 0; i < 8; i++) {
        int orow = m0 + ty*8 + i;
        if (orow < n) {
            float4 o0, o1;
            o0.x = f2lo(acc[i][0]) + b0.x; o0.y = f2hi(acc[i][0]) + b0.y;
            o0.z = f2lo(acc[i][1]) + b0.z; o0.w = f2hi(acc[i][1]) + b0.w;
            o1.x = f2lo(acc[i][2]) + b1.x; o1.y = f2hi(acc[i][2]) + b1.y;
            o1.z = f2lo(acc[i][3]) + b1.z; o1.w = f2hi(acc[i][3]) + b1.w;
            float* cp = out + (size_t)orow * DM;
            *(float4*)(cp + tx*4)      = o0;
            *(float4*)(cp + 64 + tx*4) = o1;
        }
    }
}

// ---------------- launcher ---------------------------------------------------
extern "C" void kernel_launch(void* const* d_in, const int* in_sizes, int n_in,
                              void* d_out, int out_size)
{
    const float* query     = (const float*)d_in[0];
    const float* value_fea = (const float*)d_in[1];
    const int*   coords    = (const int*)  d_in[2];
    const float* W_off     = (const float*)d_in[3];
    const float* b_off     = (const float*)d_in[4];
    const float* W_attn    = (const float*)d_in[5];
    const float* b_attn    = (const float*)d_in[6];
    const float* W_val     = (const float*)d_in[7];
    const float* b_val     = (const float*)d_in[8];
    const float* W_out     = (const float*)d_in[9];
    const float* b_out     = (const float*)d_in[10];
    float* out = (float*)d_out;

    int n = in_sizes[0] / DM;
    if (n > NMAX) n = NMAX;

    float *gv = nullptr, *goa = nullptr, *gw = nullptr;
    int *ggi = nullptr;
    cudaGetSymbolAddress((void**)&gv,  g_value);
    cudaGetSymbolAddress((void**)&goa, g_oa);
    cudaGetSymbolAddress((void**)&gw,  g_w8);
    cudaGetSymbolAddress((void**)&ggi, g_gi);

    int nb = (n + 127) / 128;

    k_init  <<<1, 32>>>();
    k_minmax<<<592, 256>>>(coords, n);
    k_params<<<1, 1>>>(n);

    // value = value_fea @ W_val + b_val (only rows < bound are gathered)
    k_gemm<<<nb, 256>>>(value_fea, W_val, DM, W_val, b_val, b_val, gv, n, 1);

    // [off | attn] = query @ [W_off | W_attn] + [b_off | b_attn]
    k_gemm<<<nb, 256>>>(query, W_off, 96, W_attn, b_off, b_attn, goa, n, 0);

    // per-row mask/softmax -> w8, gather index -> gi
    k_epi<<<(n + 31) / 32, 256>>>(goa, coords, gw, ggi, n);

    // out = (w ⊙ value[gi]) @ W_out + b_out  (gathered A, no out_pre round trip)
    k_out<<<nb, 256>>>(gw, ggi, gv, W_out, b_out, out, n);
}

// round 7
// speedup vs baseline: 2.0519x; 1.4267x over previous
#include <cuda_runtime.h>
#include <math.h>
#include <limits.h>

#define NMAX 200000
#define DM   128
#define VOXQ 8

// packed dual-fp32 FMA (sm_100+): each 32-bit lane is a full rn FMA
#define FMA2(acc, a, w) \
    asm("fma.rn.f32x2 %0, %1, %2, %0;" : "+l"(acc) : "l"(a), "l"(w))
#define BCAST2(dst, fv) \
    asm("mov.b64 %0, {%1, %1};" : "=l"(dst) : "r"(__float_as_uint(fv)))

__device__ __forceinline__ float f2lo(unsigned long long v) {
    return __uint_as_float((unsigned)v);
}
__device__ __forceinline__ float f2hi(unsigned long long v) {
    return __uint_as_float((unsigned)(v >> 32));
}

// ---------------- device globals (scratch; no allocations allowed) ----------
__device__ int g_min3[3];
__device__ int g_max3[3];
__device__ int g_count;

struct MSParams {
    int   minc[3];
    float rcf[3];
    float rv0f, rv1f;
};
__device__ MSParams g_p;

__device__ float g_oa[(size_t)NMAX * DM];     // [off | attn] logits
__device__ float g_w8[(size_t)NMAX * 8];      // per-row per-head weight
__device__ int   g_gi[(size_t)NMAX];          // per-row gather index
__device__ int   g_active[(size_t)NMAX];      // compacted active row list

// ---------------- tiny setup kernels ----------------------------------------
__global__ void k_init() {
    if (threadIdx.x < 3) {
        g_min3[threadIdx.x] = INT_MAX;
        g_max3[threadIdx.x] = INT_MIN;
    }
    if (threadIdx.x == 0) g_count = 0;
}

__global__ void k_minmax(const int* __restrict__ coords, int n) {
    int lmin0 = INT_MAX, lmin1 = INT_MAX, lmin2 = INT_MAX;
    int lmax0 = INT_MIN, lmax1 = INT_MIN, lmax2 = INT_MIN;
    for (int i = blockIdx.x * blockDim.x + threadIdx.x; i < n; i += gridDim.x * blockDim.x) {
        int c0 = coords[3*i + 0], c1 = coords[3*i + 1], c2 = coords[3*i + 2];
        lmin0 = min(lmin0, c0); lmax0 = max(lmax0, c0);
        lmin1 = min(lmin1, c1); lmax1 = max(lmax1, c1);
        lmin2 = min(lmin2, c2); lmax2 = max(lmax2, c2);
    }
    #pragma unroll
    for (int o = 16; o > 0; o >>= 1) {
        lmin0 = min(lmin0, __shfl_xor_sync(0xffffffffu, lmin0, o));
        lmin1 = min(lmin1, __shfl_xor_sync(0xffffffffu, lmin1, o));
        lmin2 = min(lmin2, __shfl_xor_sync(0xffffffffu, lmin2, o));
        lmax0 = max(lmax0, __shfl_xor_sync(0xffffffffu, lmax0, o));
        lmax1 = max(lmax1, __shfl_xor_sync(0xffffffffu, lmax1, o));
        lmax2 = max(lmax2, __shfl_xor_sync(0xffffffffu, lmax2, o));
    }
    if ((threadIdx.x & 31) == 0) {
        atomicMin(&g_min3[0], lmin0); atomicMin(&g_min3[1], lmin1); atomicMin(&g_min3[2], lmin2);
        atomicMax(&g_max3[0], lmax0); atomicMax(&g_max3[1], lmax1); atomicMax(&g_max3[2], lmax2);
    }
}

__global__ void k_params(int n) {
    if (threadIdx.x == 0 && blockIdx.x == 0) {
        int r0 = g_max3[0] - g_min3[0];
        int r1 = g_max3[1] - g_min3[1];
        int r2 = g_max3[2] - g_min3[2];
        g_p.minc[0] = g_min3[0]; g_p.minc[1] = g_min3[1]; g_p.minc[2] = g_min3[2];
        g_p.rcf[0] = (float)r0; g_p.rcf[1] = (float)r1; g_p.rcf[2] = (float)r2;
        g_p.rv0f = (float)(r0 / VOXQ + 1);
        g_p.rv1f = (float)(r1 / VOXQ + 1);
    }
}

// ---------------- SGEMM: C = A @ [W1|W2] + [b1|b2] (FFMA2 inner loop) --------
__global__ __launch_bounds__(256, 2)
void k_gemm(const float* __restrict__ A,
            const float* __restrict__ W1, int w1cols,
            const float* __restrict__ W2,
            const float* __restrict__ b1, const float* __restrict__ b2,
            float* __restrict__ C, int n)
{
    __shared__ __align__(16) float As[16 * 132];   // As[k][m]
    __shared__ __align__(16) float Ws[16 * 128];   // Ws[k][c]

    int m0 = blockIdx.x * 128;
    int tid = threadIdx.x;
    int tx = tid & 15, ty = tid >> 4;
    int w2cols = DM - w1cols;

    unsigned long long acc[8][4];
    #pragma unroll
    for (int i = 0; i < 8; i++)
        #pragma unroll
        for (int j = 0; j < 4; j++) acc[i][j] = 0ull;

    int la_r = tid >> 1;
    int la_c = (tid & 1) * 8;
    int gr = m0 + la_r;
    const float* aRow = (gr < n) ? (A + (size_t)gr * DM + la_c) : (const float*)0;
    int rW = tid >> 5;              // 0..7
    int cW = (tid & 31) << 2;       // 0..124

    float4 pa0 = make_float4(0,0,0,0), pa1 = pa0, pw0, pw1;
    if (aRow) { pa0 = *(const float4*)(aRow); pa1 = *(const float4*)(aRow + 4); }
    pw0 = (cW < w1cols) ? *(const float4*)(W1 + (size_t)rW * w1cols + cW)
                        : *(const float4*)(W2 + (size_t)rW * w2cols + (cW - w1cols));
    pw1 = (cW < w1cols) ? *(const float4*)(W1 + (size_t)(rW+8) * w1cols + cW)
                        : *(const float4*)(W2 + (size_t)(rW+8) * w2cols + (cW - w1cols));

    #pragma unroll 1
    for (int kb = 0; kb < 8; kb++) {
        As[(la_c+0)*132 + la_r] = pa0.x; As[(la_c+1)*132 + la_r] = pa0.y;
        As[(la_c+2)*132 + la_r] = pa0.z; As[(la_c+3)*132 + la_r] = pa0.w;
        As[(la_c+4)*132 + la_r] = pa1.x; As[(la_c+5)*132 + la_r] = pa1.y;
        As[(la_c+6)*132 + la_r] = pa1.z; As[(la_c+7)*132 + la_r] = pa1.w;
        *(float4*)&Ws[rW * 128 + cW]       = pw0;
        *(float4*)&Ws[(rW + 8) * 128 + cW] = pw1;
        __syncthreads();

        if (kb < 7) {
            int ko = (kb + 1) * 16;
            if (aRow) { pa0 = *(const float4*)(aRow + ko); pa1 = *(const float4*)(aRow + ko + 4); }
            pw0 = (cW < w1cols) ? *(const float4*)(W1 + (size_t)(ko+rW) * w1cols + cW)
                                : *(const float4*)(W2 + (size_t)(ko+rW) * w2cols + (cW - w1cols));
            pw1 = (cW < w1cols) ? *(const float4*)(W1 + (size_t)(ko+rW+8) * w1cols + cW)
                                : *(const float4*)(W2 + (size_t)(ko+rW+8) * w2cols + (cW - w1cols));
        }

        #pragma unroll
        for (int k = 0; k < 16; k++) {
            float4 aA = *(const float4*)&As[k*132 + ty*8];
            float4 aB = *(const float4*)&As[k*132 + ty*8 + 4];
            ulonglong2 wA = *(const ulonglong2*)&Ws[k*128 + tx*4];
            ulonglong2 wB = *(const ulonglong2*)&Ws[k*128 + 64 + tx*4];
            unsigned long long wp0 = wA.x, wp1 = wA.y, wp2 = wB.x, wp3 = wB.y;
            float av[8] = {aA.x, aA.y, aA.z, aA.w, aB.x, aB.y, aB.z, aB.w};
            #pragma unroll
            for (int i = 0; i < 8; i++) {
                unsigned long long a2;
                BCAST2(a2, av[i]);
                FMA2(acc[i][0], a2, wp0);
                FMA2(acc[i][1], a2, wp1);
                FMA2(acc[i][2], a2, wp2);
                FMA2(acc[i][3], a2, wp3);
            }
        }
        __syncthreads();
    }

    float bs0[4], bs1[4];
    #pragma unroll
    for (int j = 0; j < 4; j++) {
        int c0 = tx*4 + j, c1 = 64 + tx*4 + j;
        bs0[j] = (c0 < w1cols) ? b1[c0] : b2[c0 - w1cols];
        bs1[j] = (c1 < w1cols) ? b1[c1] : b2[c1 - w1cols];
    }
    #pragma unroll
    for (int i = 0; i < 8; i++) {
        int row = m0 + ty*8 + i;
        if (row < n) {
            float4 o0, o1;
            o0.x = f2lo(acc[i][0]) + bs0[0]; o0.y = f2hi(acc[i][0]) + bs0[1];
            o0.z = f2lo(acc[i][1]) + bs0[2]; o0.w = f2hi(acc[i][1]) + bs0[3];
            o1.x = f2lo(acc[i][2]) + bs1[0]; o1.y = f2hi(acc[i][2]) + bs1[1];
            o1.z = f2lo(acc[i][3]) + bs1[2]; o1.w = f2hi(acc[i][3]) + bs1[3];
            float* cp = C + (size_t)row * DM;
            *(float4*)(cp + tx*4)      = o0;
            *(float4*)(cp + 64 + tx*4) = o1;
        }
    }
}

// ---------------- epilogue: mask + softmax -> w8, gi, active list, out=b_out -
__global__ __launch_bounds__(256)
void k_epi(const float* __restrict__ oa, const int* __restrict__ coords,
           const float* __restrict__ b_out,
           float* __restrict__ w8, int* __restrict__ gi_out,
           int* __restrict__ act_list, float* __restrict__ out, int n)
{
    __shared__ __align__(16) float srow[32][132];
    __shared__ __align__(16) float sbout[128];
    __shared__ int s_act[32];

    int r0 = blockIdx.x * 32;
    int tid = threadIdx.x;

    if (tid < 128) sbout[tid] = b_out[tid];
    if (tid < 32)  s_act[tid] = 0;
    for (int i = tid; i < 32 * 32; i += 256) {
        int r  = i >> 5;
        int c4 = (i & 31) << 2;
        int row = r0 + r;
        float4 v = make_float4(0.f,0.f,0.f,0.f);
        if (row < n) v = *(const float4*)(oa + (size_t)row * DM + c4);
        *(float4*)&srow[r][c4] = v;
    }
    __syncthreads();

    int r = tid >> 3;
    int h = tid & 7;
    int row = r0 + r;
    bool valid = row < n;

    if (valid) {
        if (h == 0) {
            int c0 = coords[3*row + 0], c1 = coords[3*row + 1], c2 = coords[3*row + 2];
            float i0 = (float)(c0 - g_p.minc[0]) * 0.125f;
            float i1 = (float)(c1 - g_p.minc[1]) * 0.125f;
            float i2 = (float)(c2 - g_p.minc[2]) * 0.125f;
            float flat = i0 * g_p.rv1f * g_p.rv0f + i1 * g_p.rv0f + i2;
            int gi = (int)floorf(flat);
            gi = gi < 0 ? 0 : (gi > n - 1 ? n - 1 : gi);
            gi_out[row] = gi;
        }

        float l[4], e[4];
        #pragma unroll
        for (int p = 0; p < 4; p++) l[p] = srow[r][96 + h*4 + p];
        float mx = fmaxf(fmaxf(l[0], l[1]), fmaxf(l[2], l[3]));
        float s = 0.f;
        #pragma unroll
        for (int p = 0; p < 4; p++) { e[p] = expf(l[p] - mx); s += e[p]; }

        float rc0 = g_p.rcf[0], rc1 = g_p.rcf[1], rc2 = g_p.rcf[2];
        float num = 0.f;
        #pragma unroll
        for (int p = 0; p < 4; p++) {
            int base = (h*4 + p) * 3;
            float t0 = (srow[r][base + 0] * rc0) * 0.5f;
            float t1 = (srow[r][base + 1] * rc1) * 0.5f;
            float t2 = (srow[r][base + 2] * rc2) * 0.5f;
            int a0 = (int)t0, a1 = (int)t1, a2 = (int)t2;   // trunc toward 0 (.astype(int32))
            unsigned u = (unsigned)a0 | (unsigned)a1 | (unsigned)a2;
            if (u < 8u) num += e[p];
        }
        w8[(size_t)row * 8 + h] = num / s;
        if (num != 0.f) s_act[r] = 1;    // benign race: all writers store 1
    }
    __syncthreads();

    if (valid) {
        // fill out[row] = b_out (exact result for inactive rows; active rows
        // are overwritten by k_active later in the same stream)
        float* op = out + (size_t)row * DM + h*16;
        *(float4*)(op + 0)  = *(const float4*)&sbout[h*16 + 0];
        *(float4*)(op + 4)  = *(const float4*)&sbout[h*16 + 4];
        *(float4*)(op + 8)  = *(const float4*)&sbout[h*16 + 8];
        *(float4*)(op + 12) = *(const float4*)&sbout[h*16 + 12];

        if (h == 0 && s_act[r]) {
            int slot = atomicAdd(&g_count, 1);
            act_list[slot] = row;
        }
    }
}

// ---------------- active rows: out[row] = (w ⊙ (vf[gi]@W_val+b_val)) @ W_out + b_out
__global__ __launch_bounds__(128)
void k_active(const float* __restrict__ value_fea,
              const float* __restrict__ W_val, const float* __restrict__ b_val,
              const float* __restrict__ W_out, const float* __restrict__ b_out,
              const float* __restrict__ w8, const int* __restrict__ gi,
              const int* __restrict__ act_list, float* __restrict__ out)
{
    __shared__ float svf[128];
    __shared__ float spre[128];
    __shared__ float sw[8];

    int tid = threadIdx.x;
    int cnt = g_count;

    for (int idx = blockIdx.x; idx < cnt; idx += gridDim.x) {
        int row = act_list[idx];
        if (tid < 8) sw[tid] = w8[(size_t)row * 8 + tid];
        int g = gi[row];
        svf[tid] = value_fea[(size_t)g * DM + tid];
        __syncthreads();

        // value row = value_fea[g] @ W_val + b_val, scaled by head weight
        float acc = 0.f;
        #pragma unroll 8
        for (int k = 0; k < DM; k++)
            acc = fmaf(svf[k], W_val[k * DM + tid], acc);
        acc += b_val[tid];
        spre[tid] = acc * sw[tid >> 4];
        __syncthreads();

        // out row = pre @ W_out + b_out
        float acc2 = 0.f;
        #pragma unroll 8
        for (int k = 0; k < DM; k++)
            acc2 = fmaf(spre[k], W_out[k * DM + tid], acc2);
        out[(size_t)row * DM + tid] = acc2 + b_out[tid];
        __syncthreads();
    }
}

// ---------------- launcher ---------------------------------------------------
extern "C" void kernel_launch(void* const* d_in, const int* in_sizes, int n_in,
                              void* d_out, int out_size)
{
    const float* query     = (const float*)d_in[0];
    const float* value_fea = (const float*)d_in[1];
    const int*   coords    = (const int*)  d_in[2];
    const float* W_off     = (const float*)d_in[3];
    const float* b_off     = (const float*)d_in[4];
    const float* W_attn    = (const float*)d_in[5];
    const float* b_attn    = (const float*)d_in[6];
    const float* W_val     = (const float*)d_in[7];
    const float* b_val     = (const float*)d_in[8];
    const float* W_out     = (const float*)d_in[9];
    const float* b_out     = (const float*)d_in[10];
    float* out = (float*)d_out;

    int n = in_sizes[0] / DM;
    if (n > NMAX) n = NMAX;

    float *goa = nullptr, *gw = nullptr;
    int *ggi = nullptr, *gact = nullptr;
    cudaGetSymbolAddress((void**)&goa,  g_oa);
    cudaGetSymbolAddress((void**)&gw,   g_w8);
    cudaGetSymbolAddress((void**)&ggi,  g_gi);
    cudaGetSymbolAddress((void**)&gact, g_active);

    int nb = (n + 127) / 128;

    k_init  <<<1, 32>>>();
    k_minmax<<<592, 256>>>(coords, n);
    k_params<<<1, 1>>>(n);

    // [off | attn] = query @ [W_off | W_attn] + [b_off | b_attn]  (the one dense GEMM)
    k_gemm<<<nb, 256>>>(query, W_off, 96, W_attn, b_off, b_attn, goa, n);

    // mask + softmax -> w8, gi, active list; fill out = b_out (exact for inactive rows)
    k_epi<<<(n + 31) / 32, 256>>>(goa, coords, b_out, gw, ggi, gact, out, n);

    // recompute the few active rows end-to-end (value GEMM + out GEMM on ~1e-3 of rows)
    k_active<<<1184, 128>>>(value_fea, W_val, b_val, W_out, b_out, gw, ggi, gact, out);
}